// round 12
// baseline (speedup 1.0000x reference)
#include <cuda_runtime.h>
#include <cstdint>

#define ALPHA 0.9048374180359595f   // exp(-1/10), rounds to same f32 as JAX
#define BT 12800                     // B*T = 128*100

// Layer-1 pooled conv output, layout [sample = b*100+t][256 = c*64+y*8+x]
__device__ float g_h1[BT * 256];

// ---------------------------------------------------------------------------
// Stage 1: folded conv1(5x5,pad2)+pool4 as 8x8 stride-4 conv, register-tiled.
// 8 samples/block, 128 threads: thread = (sl = tid>>4, tile = tid&15) computes
// a 2x2 tile of pooled positions x all 4 output channels (16 accumulators).
// Per tap: 1 uniform float4 weight broadcast + 4 x-loads + 16 FMA.
//
// smem x layout (per sample, flat stride 3169 floats - odd on purpose):
//   xs[sl*3169 + ((ic*4 + r)*36 + row)*11 + q]  holds x[ic][row-2][4(q-1)+r]
// row pitch 11 => compute-lane banks 88*ty+2*tx mod 32 all distinct;
// odd sample stride => the two samples in a warp land on disjoint bank parity.
// ---------------------------------------------------------------------------
#define S1_STRIDE 3169
#define S1_SMEM   (8 * S1_STRIDE)          // 25352 floats = 101408 B

__global__ void __launch_bounds__(128) k_stage1(const float* __restrict__ x,
                                                const float* __restrict__ w1) {
    extern __shared__ float xs[];
    __shared__ float4 wq[128];             // [(ic*8+dy)*8+dx] -> {c0,c1,c2,c3}
    int tid = threadIdx.x;

    // fold conv1+pool weights in-block (idempotent, L1/L2-cached reads)
    float* wqf = (float*)wq;
    for (int e = tid; e < 512; e += 128) {
        int c = e & 3, tap = e >> 2;
        int dx = tap & 7, dy = (tap >> 3) & 7, ic = tap >> 6;
        int iy0 = dy > 3 ? dy - 3 : 0, iy1 = dy < 4 ? dy : 4;
        int ix0 = dx > 3 ? dx - 3 : 0, ix1 = dx < 4 ? dx : 4;
        float s = 0.f;
        for (int iy = iy0; iy <= iy1; iy++)
            for (int ix = ix0; ix <= ix1; ix++)
                s += w1[((c * 2 + ic) * 5 + iy) * 5 + ix];
        wqf[e] = s * (1.0f / 16.0f);
    }
    for (int idx = tid; idx < S1_SMEM; idx += 128) xs[idx] = 0.f;
    __syncthreads();

    // load 8 samples (16384 floats) coalesced; scatter to split layout
    const float* xg = x + (size_t)blockIdx.x * 16384;
#pragma unroll 8
    for (int k = 0; k < 128; k++) {
        int idx = tid + k * 128;
        int sl = idx >> 11, rem = idx & 2047;
        int ic = rem >> 10, yy = (rem >> 5) & 31, cc = rem & 31;
        xs[sl * S1_STRIDE + ((ic * 4 + (cc & 3)) * 36 + yy + 2) * 11 + (cc >> 2) + 1] = xg[idx];
    }
    __syncthreads();

    int sl = tid >> 4, tile = tid & 15, ty = tile >> 2, tx = tile & 3;
    const float* xb = xs + sl * S1_STRIDE;

    float4 A00 = {0,0,0,0}, A01 = {0,0,0,0}, A10 = {0,0,0,0}, A11 = {0,0,0,0};
#pragma unroll
    for (int ic = 0; ic < 2; ic++)
#pragma unroll
        for (int dy = 0; dy < 8; dy++) {
            int r0 = 8 * ty + dy;                     // row for j=0 (j=1: +4)
#pragma unroll
            for (int dx = 0; dx < 8; dx++) {
                float4 w = wq[(ic * 8 + dy) * 8 + dx];     // uniform broadcast
                int pl = (dx + 2) & 3, qb = 2 * tx + ((dx + 2) >> 2);
                const float* p0 = xb + ((ic * 4 + pl) * 36 + r0) * 11 + qb;
                float x00 = p0[0],  x01 = p0[1];
                float x10 = p0[44], x11 = p0[45];          // row+4 => +44
                A00.x = fmaf(x00, w.x, A00.x); A00.y = fmaf(x00, w.y, A00.y);
                A00.z = fmaf(x00, w.z, A00.z); A00.w = fmaf(x00, w.w, A00.w);
                A01.x = fmaf(x01, w.x, A01.x); A01.y = fmaf(x01, w.y, A01.y);
                A01.z = fmaf(x01, w.z, A01.z); A01.w = fmaf(x01, w.w, A01.w);
                A10.x = fmaf(x10, w.x, A10.x); A10.y = fmaf(x10, w.y, A10.y);
                A10.z = fmaf(x10, w.z, A10.z); A10.w = fmaf(x10, w.w, A10.w);
                A11.x = fmaf(x11, w.x, A11.x); A11.y = fmaf(x11, w.y, A11.y);
                A11.z = fmaf(x11, w.z, A11.z); A11.w = fmaf(x11, w.w, A11.w);
            }
        }

    float* o = g_h1 + ((size_t)blockIdx.x * 8 + sl) * 256 + (2 * ty) * 8 + 2 * tx;
    o[  0] = A00.x; o[  1] = A01.x; o[  8] = A10.x; o[  9] = A11.x;
    o[ 64] = A00.y; o[ 65] = A01.y; o[ 72] = A10.y; o[ 73] = A11.y;
    o[128] = A00.z; o[129] = A01.z; o[136] = A10.z; o[137] = A11.z;
    o[192] = A00.w; o[193] = A01.w; o[200] = A10.w; o[201] = A11.w;
}

// ---------------------------------------------------------------------------
// Stages 2-5 fused: per-batch temporal scan (block = one b, 256 threads).
//   layer-1 exp_leak+LIF (256 lanes) -> spike pad (double-buffered, 1 barrier
//   per step) -> folded conv2 4x4 stride-2 (128 lanes) -> layer-2 exp_leak+LIF
//   -> spikes captured as ballot bitmasks; linear [2,128] deferred post-loop.
// ---------------------------------------------------------------------------
__global__ void __launch_bounds__(256) k_scan(const float* __restrict__ w2,
                                              const float* __restrict__ lin_w,
                                              float* __restrict__ out) {
    __shared__ float spad[2][4][10][10];   // double-buffered, borders stay 0
    __shared__ float wf2[512];             // folded conv2+pool, [tap][c2]
    __shared__ float lws2[256];            // interleaved [f][o]
    __shared__ uint32_t sbits[100][4];     // layer-2 spike masks per step
    int tid = threadIdx.x;
    int b = blockIdx.x;

    for (int idx = tid; idx < 800; idx += 256) ((float*)spad)[idx] = 0.f;
    // fold conv2+pool weights in-block: wf2[(ic*16+dy*4+dx)*8 + c] (x0.25)
    for (int e = tid; e < 512; e += 256) {
        int c = e & 7, tap = e >> 3;
        int dx = tap & 3, dy = (tap >> 2) & 3, ic = tap >> 4;
        int iy0 = dy > 1 ? dy - 1 : 0, iy1 = dy < 2 ? dy : 2;
        int ix0 = dx > 1 ? dx - 1 : 0, ix1 = dx < 2 ? dx : 2;
        float s = 0.f;
        for (int iy = iy0; iy <= iy1; iy++)
            for (int ix = ix0; ix <= ix1; ix++)
                s += w2[((c * 4 + ic) * 3 + iy) * 3 + ix];
        wf2[e] = s * 0.25f;
    }
    lws2[tid] = lin_w[(tid & 1) * 128 + (tid >> 1)];   // lws2[f*2+o]

    int c1 = tid >> 6, y1 = (tid >> 3) & 7, x1 = tid & 7;
    int c2 = tid >> 4, y2 = (tid >> 2) & 3, x2 = tid & 3;   // valid for tid<128
    int lane = tid & 31, warp = tid >> 5;

    float v1m = 0.f, v1u = 0.f, v2m = 0.f, v2u = 0.f;
    const float* hp = g_h1 + (size_t)b * 100 * 256;
    float hcur = hp[tid];
    float hnext = hp[256 + tid];
    __syncthreads();

    for (int t = 0; t < 100; t++) {
        float h = hcur;
        hcur = hnext;
        if (t < 98) hnext = hp[(t + 2) * 256 + tid];   // depth-2 prefetch

        // layer-1 exp_leak membrane, then LIF (membrane-subtract reset)
        v1m = ALPHA * v1m + h;
        v1u = ALPHA * v1u + v1m;
        float s = (v1u >= 1.0f) ? 1.0f : 0.0f;
        v1u -= s;
        int p = t & 1;
        spad[p][c1][y1 + 1][x1 + 1] = s;
        __syncthreads();   // single barrier: double-buffer removes WAR hazard

        if (tid < 128) {
            // folded conv2+pool2: 4x4 stride-2 window over spike pad
            float a0 = 0.f, a1 = 0.f, a2 = 0.f, a3 = 0.f;
#pragma unroll
            for (int dy = 0; dy < 4; dy++)
#pragma unroll
                for (int dx = 0; dx < 4; dx++) {
                    int tp = dy * 4 + dx;
                    a0 = fmaf(wf2[(0 + tp) * 8 + c2],  spad[p][0][2*y2+dy][2*x2+dx], a0);
                    a1 = fmaf(wf2[(16 + tp) * 8 + c2], spad[p][1][2*y2+dy][2*x2+dx], a1);
                    a2 = fmaf(wf2[(32 + tp) * 8 + c2], spad[p][2][2*y2+dy][2*x2+dx], a2);
                    a3 = fmaf(wf2[(48 + tp) * 8 + c2], spad[p][3][2*y2+dy][2*x2+dx], a3);
                }
            float acc = (a0 + a1) + (a2 + a3);

            // layer-2 exp_leak + LIF
            v2m = ALPHA * v2m + acc;
            v2u = ALPHA * v2u + v2m;
            bool sp = (v2u >= 1.0f);
            v2u -= sp ? 1.0f : 0.0f;

            uint32_t m = __ballot_sync(0xffffffffu, sp);  // warps 0-3 full
            if (lane == 0) sbits[t][warp] = m;
        }
    }
    __syncthreads();

    // Deferred linear: out[b,t,o] = sum_f lw[o,f] * spike[t,f]
    if (tid < 200) {
        int t = tid >> 1, o = tid & 1;
        float acc = 0.f;
#pragma unroll
        for (int w = 0; w < 4; w++) {
            uint32_t m = sbits[t][w];
#pragma unroll
            for (int j = 0; j < 32; j++)
                acc += (m >> j & 1u) ? lws2[(w * 32 + j) * 2 + o] : 0.f;
        }
        out[(b * 100 + t) * 2 + o] = acc;
    }
}

// ---------------------------------------------------------------------------
extern "C" void kernel_launch(void* const* d_in, const int* in_sizes, int n_in,
                              void* d_out, int out_size) {
    // Rank-based input binding: invariant to metadata ordering AND units.
    int xi = 0;
    for (int i = 1; i < n_in; i++)
        if (in_sizes[i] > in_sizes[xi]) xi = i;

    int rest[3]; int nr = 0;
    for (int i = 0; i < n_in && nr < 3; i++)
        if (i != xi) rest[nr++] = i;
    for (int a = 0; a < 2; a++)
        for (int bq = 0; bq < 2 - a; bq++)
            if (in_sizes[rest[bq]] > in_sizes[rest[bq + 1]]) {
                int tmp = rest[bq]; rest[bq] = rest[bq + 1]; rest[bq + 1] = tmp;
            }

    const float* x  = (const float*)d_in[xi];       // [128,100,2,32,32]
    const float* w1 = (const float*)d_in[rest[0]];  // [4,2,5,5]   (200)
    const float* lw = (const float*)d_in[rest[1]];  // [2,128]     (256)
    const float* w2 = (const float*)d_in[rest[2]];  // [8,4,3,3]   (288)
    float* out = (float*)d_out;                     // [128,100,2]

    cudaFuncSetAttribute(k_stage1, cudaFuncAttributeMaxDynamicSharedMemorySize,
                         S1_SMEM * (int)sizeof(float));
    k_stage1<<<1600, 128, S1_SMEM * sizeof(float)>>>(x, w1);
    k_scan<<<128, 256>>>(w2, lw, out);
}